// round 2
// baseline (speedup 1.0000x reference)
#include <cuda_runtime.h>

// Problem constants
#define Bsz  8
#define Ssz  512
#define Dsz  1024
#define Hn   16
#define HDim 64
#define Fsz  4096
#define Lnum 6
#define Msz  (Bsz*Ssz)   // 4096 rows

// Scratch: x, tmp, q, k, v, ctx (each M*D) + ff (M*F)  => ~168 MB
__device__ float g_scratch[(size_t)Msz*Dsz*6 + (size_t)Msz*Fsz];

// ---------------------------------------------------------------------------
// Embedding: x = tok_emb[src]*sqrt(D) + pos_emb[s]
// ---------------------------------------------------------------------------
__global__ void embed_kernel(const int* __restrict__ src,
                             const float* __restrict__ tok,
                             const float* __restrict__ pos,
                             float* __restrict__ x)
{
    int i = blockIdx.x * blockDim.x + threadIdx.x;   // over M*D
    int m = i >> 10;
    int d = i & 1023;
    int s = m & (Ssz - 1);
    x[i] = tok[(size_t)src[m] * Dsz + d] * 32.0f + pos[s * Dsz + d];
}

// ---------------------------------------------------------------------------
// SGEMM: C[M,N] = A[M,K] @ B[K,N] + bias[N]  (+ epilogue)
// EPI: 0 = bias only, 1 = bias+relu, 2 = bias + residual R
// 128x128 tile, BK=8, 256 threads, 8x8 per-thread microtile.
// ---------------------------------------------------------------------------
template<int EPI>
__global__ __launch_bounds__(256)
void sgemm_kernel(const float* __restrict__ A, const float* __restrict__ Bm,
                  const float* __restrict__ bias, const float* __restrict__ Rm,
                  float* __restrict__ C, int Mn, int Nn, int Kn)
{
    __shared__ float As[8][128];
    __shared__ float Bs[8][128];
    const int tid = threadIdx.x;
    const int bm = blockIdx.y * 128;
    const int bn = blockIdx.x * 128;
    const int arow = tid >> 1;            // 0..127
    const int acol = (tid & 1) << 2;      // 0 or 4
    const int brow = tid >> 5;            // 0..7
    const int bcol = (tid & 31) << 2;     // 0..124
    const int tx = (tid & 15) << 3;       // 0..120
    const int ty = (tid >> 4) << 3;       // 0..120

    float acc[8][8];
    #pragma unroll
    for (int i = 0; i < 8; i++)
        #pragma unroll
        for (int j = 0; j < 8; j++) acc[i][j] = 0.f;

    const float* Ap = A  + (size_t)(bm + arow) * Kn + acol;
    const float* Bp = Bm + (size_t)brow * Nn + bn + bcol;

    for (int k0 = 0; k0 < Kn; k0 += 8) {
        float4 av = *(const float4*)(Ap + k0);
        float4 bv = *(const float4*)(Bp + (size_t)k0 * Nn);
        __syncthreads();
        As[acol + 0][arow] = av.x;
        As[acol + 1][arow] = av.y;
        As[acol + 2][arow] = av.z;
        As[acol + 3][arow] = av.w;
        *(float4*)&Bs[brow][bcol] = bv;
        __syncthreads();
        #pragma unroll
        for (int kk = 0; kk < 8; ++kk) {
            float a[8], b[8];
            #pragma unroll
            for (int i = 0; i < 8; i++) a[i] = As[kk][ty + i];
            #pragma unroll
            for (int j = 0; j < 8; j++) b[j] = Bs[kk][tx + j];
            #pragma unroll
            for (int i = 0; i < 8; i++)
                #pragma unroll
                for (int j = 0; j < 8; j++)
                    acc[i][j] = fmaf(a[i], b[j], acc[i][j]);
        }
    }

    #pragma unroll
    for (int i = 0; i < 8; i++) {
        int m = bm + ty + i;
        #pragma unroll
        for (int j = 0; j < 8; j++) {
            int n = bn + tx + j;
            float v = acc[i][j] + bias[n];
            if (EPI == 1) v = fmaxf(v, 0.f);
            if (EPI == 2) v += Rm[(size_t)m * Nn + n];
            C[(size_t)m * Nn + n] = v;
        }
    }
}

// ---------------------------------------------------------------------------
// Flash attention (fp32, online softmax).
// Smem row stride = 68 floats (16B-aligned for float4; 68 mod 32 = 4 so the
// 8 distinct rows a warp touches land in distinct bank groups).
// ---------------------------------------------------------------------------
#define FPAD 68
#define FTILE (64 * FPAD)   // 4352 floats per array

__global__ __launch_bounds__(256)
void flash_kernel(const float* __restrict__ Qg, const float* __restrict__ Kg,
                  const float* __restrict__ Vg, const int* __restrict__ mask,
                  float* __restrict__ ctx)
{
    extern __shared__ float smf[];
    float* Qs  = smf;                 // [64][FPAD]
    float* KsT = smf + FTILE;         // [d][c]
    float* Vs  = smf + 2 * FTILE;     // [k][c]
    float* Ps  = smf + 3 * FTILE;     // [r][k]
    int*   msk = (int*)(smf + 4 * FTILE);  // [64]

    const int qt = blockIdx.x, h = blockIdx.y, b = blockIdx.z;
    const int tid = threadIdx.x;
    const int r  = tid >> 2;            // 0..63
    const int cg = (tid & 3) << 4;      // 0,16,32,48

    const float* Qb = Qg + ((size_t)(b * Ssz) + qt * 64 + r) * Dsz + h * HDim;
    #pragma unroll
    for (int i = 0; i < 16; i += 4)
        *(float4*)&Qs[r * FPAD + cg + i] = *(const float4*)(Qb + cg + i);

    float m_i = -1e30f, l_i = 0.f;
    float acc[16];
    #pragma unroll
    for (int j = 0; j < 16; j++) acc[j] = 0.f;

    const float invscale = 1.0f / 32.0f;   // 1/sqrt(D)

    for (int kt = 0; kt < Ssz / 64; ++kt) {
        const int k0 = kt * 64;
        const float* Kb = Kg + ((size_t)(b * Ssz) + k0 + r) * Dsz + h * HDim;
        const float* Vb = Vg + ((size_t)(b * Ssz) + k0 + r) * Dsz + h * HDim;
        __syncthreads();   // previous tile's PV done before overwrite
        #pragma unroll
        for (int i = 0; i < 16; i++)
            KsT[(cg + i) * FPAD + r] = Kb[cg + i];
        #pragma unroll
        for (int i = 0; i < 16; i += 4)
            *(float4*)&Vs[r * FPAD + cg + i] = *(const float4*)(Vb + cg + i);
        if (tid < 64) msk[tid] = mask[b * Ssz + k0 + tid];
        __syncthreads();

        // S = Q K^T (this thread: row r, cols cg..cg+15)
        float s[16];
        #pragma unroll
        for (int j = 0; j < 16; j++) s[j] = 0.f;
        #pragma unroll 8
        for (int d = 0; d < 64; ++d) {
            float qv = Qs[r * FPAD + d];
            #pragma unroll
            for (int j = 0; j < 16; j++)
                s[j] = fmaf(qv, KsT[d * FPAD + cg + j], s[j]);
        }
        // scale + mask + row max
        float mx = -1e30f;
        #pragma unroll
        for (int j = 0; j < 16; j++) {
            float e = s[j] * invscale;
            if (msk[cg + j] == 0) e = -1e10f;
            s[j] = e;
            mx = fmaxf(mx, e);
        }
        mx = fmaxf(mx, __shfl_xor_sync(0xffffffffu, mx, 1));
        mx = fmaxf(mx, __shfl_xor_sync(0xffffffffu, mx, 2));
        float m_new = fmaxf(m_i, mx);
        float alpha = __expf(m_i - m_new);
        float lsum = 0.f;
        #pragma unroll
        for (int j = 0; j < 16; j++) {
            float p = __expf(s[j] - m_new);
            s[j] = p;
            lsum += p;
        }
        lsum += __shfl_xor_sync(0xffffffffu, lsum, 1);
        lsum += __shfl_xor_sync(0xffffffffu, lsum, 2);
        l_i = l_i * alpha + lsum;
        m_i = m_new;
        #pragma unroll
        for (int j = 0; j < 16; j++) acc[j] *= alpha;
        #pragma unroll
        for (int j = 0; j < 16; j++) Ps[r * FPAD + cg + j] = s[j];
        __syncwarp();   // P row r written/read by same warp's lanes
        #pragma unroll 8
        for (int k = 0; k < 64; ++k) {
            float pv = Ps[r * FPAD + k];
            #pragma unroll
            for (int j = 0; j < 16; j++)
                acc[j] = fmaf(pv, Vs[k * FPAD + cg + j], acc[j]);
        }
    }
    float invl = 1.f / l_i;
    float* Ob = ctx + ((size_t)(b * Ssz) + qt * 64 + r) * Dsz + h * HDim;
    #pragma unroll
    for (int j = 0; j < 16; j++)
        Ob[cg + j] = acc[j] * invl;
}

// ---------------------------------------------------------------------------
// LayerNorm over D=1024
// ---------------------------------------------------------------------------
__global__ __launch_bounds__(256)
void ln_kernel(const float* __restrict__ in, const float* __restrict__ g,
               const float* __restrict__ be, float* __restrict__ out)
{
    const int row = blockIdx.x;
    const int tid = threadIdx.x;
    const float* p = in + (size_t)row * Dsz;
    float4 v = *(const float4*)(p + tid * 4);
    float s  = v.x + v.y + v.z + v.w;
    float s2 = v.x*v.x + v.y*v.y + v.z*v.z + v.w*v.w;
    #pragma unroll
    for (int o = 16; o > 0; o >>= 1) {
        s  += __shfl_xor_sync(0xffffffffu, s,  o);
        s2 += __shfl_xor_sync(0xffffffffu, s2, o);
    }
    __shared__ float ws[8], ws2[8];
    if ((tid & 31) == 0) { ws[tid >> 5] = s; ws2[tid >> 5] = s2; }
    __syncthreads();
    if (tid < 32) {
        float a  = (tid < 8) ? ws[tid]  : 0.f;
        float a2 = (tid < 8) ? ws2[tid] : 0.f;
        #pragma unroll
        for (int o = 4; o > 0; o >>= 1) {
            a  += __shfl_xor_sync(0xffffffffu, a,  o);
            a2 += __shfl_xor_sync(0xffffffffu, a2, o);
        }
        if (tid == 0) { ws[0] = a; ws2[0] = a2; }
    }
    __syncthreads();
    float mean = ws[0] * (1.f / Dsz);
    float var  = ws2[0] * (1.f / Dsz) - mean * mean;
    float rstd = rsqrtf(var + 1e-5f);
    float4 gv = *(const float4*)(g  + tid * 4);
    float4 bv = *(const float4*)(be + tid * 4);
    float4 o;
    o.x = (v.x - mean) * rstd * gv.x + bv.x;
    o.y = (v.y - mean) * rstd * gv.y + bv.y;
    o.z = (v.z - mean) * rstd * gv.z + bv.z;
    o.w = (v.w - mean) * rstd * gv.w + bv.w;
    *(float4*)(out + (size_t)row * Dsz + tid * 4) = o;
}

// ---------------------------------------------------------------------------
// Launcher
// ---------------------------------------------------------------------------
extern "C" void kernel_launch(void* const* d_in, const int* in_sizes, int n_in,
                              void* d_out, int out_size)
{
    const int*   src  = (const int*)d_in[0];
    const int*   mask = (const int*)d_in[1];
    const float* tok  = (const float*)d_in[2];
    const float* pos  = (const float*)d_in[3];
    const float* Wq   = (const float*)d_in[4];
    const float* bq   = (const float*)d_in[5];
    const float* Wk   = (const float*)d_in[6];
    const float* bk   = (const float*)d_in[7];
    const float* Wv   = (const float*)d_in[8];
    const float* bv   = (const float*)d_in[9];
    const float* Wo   = (const float*)d_in[10];
    const float* bo   = (const float*)d_in[11];
    const float* g1   = (const float*)d_in[12];
    const float* be1  = (const float*)d_in[13];
    const float* g2   = (const float*)d_in[14];
    const float* be2  = (const float*)d_in[15];
    const float* W1   = (const float*)d_in[16];
    const float* bf1  = (const float*)d_in[17];
    const float* W2   = (const float*)d_in[18];
    const float* bf2  = (const float*)d_in[19];

    float* scratch = nullptr;
    cudaGetSymbolAddress((void**)&scratch, g_scratch);
    const size_t MD = (size_t)Msz * Dsz;
    float* x   = scratch;
    float* tmp = scratch + MD;
    float* q   = scratch + 2 * MD;
    float* k   = scratch + 3 * MD;
    float* v   = scratch + 4 * MD;
    float* ctx = scratch + 5 * MD;
    float* ff  = scratch + 6 * MD;

    const int FLASH_SMEM = 4 * FTILE * 4 + 64 * 4;   // 69888 B
    cudaFuncSetAttribute(flash_kernel,
                         cudaFuncAttributeMaxDynamicSharedMemorySize, FLASH_SMEM);

    embed_kernel<<<(Msz * Dsz) / 256, 256>>>(src, tok, pos, x);

    dim3 g_dd(Dsz / 128, Msz / 128);   // 8 x 32
    dim3 g_df(Fsz / 128, Msz / 128);   // 32 x 32
    dim3 g_fl(Ssz / 64, Hn, Bsz);      // 8 x 16 x 8

    for (int i = 0; i < Lnum; i++) {
        const float* Wqi = Wq + (size_t)i * Dsz * Dsz;
        const float* Wki = Wk + (size_t)i * Dsz * Dsz;
        const float* Wvi = Wv + (size_t)i * Dsz * Dsz;
        const float* Woi = Wo + (size_t)i * Dsz * Dsz;
        const float* W1i = W1 + (size_t)i * Dsz * Fsz;
        const float* W2i = W2 + (size_t)i * Fsz * Dsz;
        const float* bqi = bq + (size_t)i * Dsz;
        const float* bki = bk + (size_t)i * Dsz;
        const float* bvi = bv + (size_t)i * Dsz;
        const float* boi = bo + (size_t)i * Dsz;
        const float* b1i = bf1 + (size_t)i * Fsz;
        const float* b2i = bf2 + (size_t)i * Dsz;

        sgemm_kernel<0><<<g_dd, 256>>>(x, Wqi, bqi, nullptr, q, Msz, Dsz, Dsz);
        sgemm_kernel<0><<<g_dd, 256>>>(x, Wki, bki, nullptr, k, Msz, Dsz, Dsz);
        sgemm_kernel<0><<<g_dd, 256>>>(x, Wvi, bvi, nullptr, v, Msz, Dsz, Dsz);

        flash_kernel<<<g_fl, 256, FLASH_SMEM>>>(q, k, v, mask, ctx);

        sgemm_kernel<2><<<g_dd, 256>>>(ctx, Woi, boi, x, tmp, Msz, Dsz, Dsz);
        ln_kernel<<<Msz, 256>>>(tmp, g1 + (size_t)i * Dsz, be1 + (size_t)i * Dsz, x);

        sgemm_kernel<1><<<g_df, 256>>>(x, W1i, b1i, nullptr, ff, Msz, Fsz, Dsz);
        sgemm_kernel<2><<<g_dd, 256>>>(ff, W2i, b2i, x, tmp, Msz, Dsz, Fsz);

        float* lnout = (i == Lnum - 1) ? (float*)d_out : x;
        ln_kernel<<<Msz, 256>>>(tmp, g2 + (size_t)i * Dsz, be2 + (size_t)i * Dsz, lnout);
    }
}

// round 3
// speedup vs baseline: 1.3703x; 1.3703x over previous
#include <cuda_runtime.h>
#include <cuda_bf16.h>
#include <cstdint>

// Problem constants
#define Bsz  8
#define Ssz  512
#define Dsz  1024
#define Hn   16
#define HDim 64
#define Fsz  4096
#define Lnum 6
#define Msz  (Bsz*Ssz)   // 4096 rows

__device__ float g_scratch[(size_t)Msz*Dsz*6 + (size_t)Msz*Fsz];

// ---------------------------------------------------------------------------
// Embedding
// ---------------------------------------------------------------------------
__global__ void embed_kernel(const int* __restrict__ src,
                             const float* __restrict__ tok,
                             const float* __restrict__ pos,
                             float* __restrict__ x)
{
    int i = blockIdx.x * blockDim.x + threadIdx.x;
    int m = i >> 10;
    int d = i & 1023;
    int s = m & (Ssz - 1);
    x[i] = tok[(size_t)src[m] * Dsz + d] * 32.0f + pos[s * Dsz + d];
}

// ---------------------------------------------------------------------------
// Tensor-core GEMM with split-bf16 emulation of fp32.
// C[M,N] = A[M,K] @ B[K,N] + bias (+relu | +residual)
// A = Ah + Al (bf16 hi/lo), B = Bh + Bl. C += Ah*Bh + Ah*Bl + Al*Bh.
// Block tile 128x128, BK=32, 256 threads = 8 warps (2 M x 4 N), warp 64x32.
// ---------------------------------------------------------------------------
__device__ __forceinline__ uint32_t pack_bf2(__nv_bfloat16 a, __nv_bfloat16 b) {
    return ((uint32_t)__bfloat16_as_ushort(b) << 16) | (uint32_t)__bfloat16_as_ushort(a);
}

__device__ __forceinline__ void ldsm_x4(uint32_t r[4], const void* p) {
    uint32_t addr = (uint32_t)__cvta_generic_to_shared(p);
    asm volatile("ldmatrix.sync.aligned.m8n8.x4.shared.b16 {%0,%1,%2,%3}, [%4];"
                 : "=r"(r[0]), "=r"(r[1]), "=r"(r[2]), "=r"(r[3]) : "r"(addr));
}
__device__ __forceinline__ void ldsm_x4_t(uint32_t r[4], const void* p) {
    uint32_t addr = (uint32_t)__cvta_generic_to_shared(p);
    asm volatile("ldmatrix.sync.aligned.m8n8.x4.trans.shared.b16 {%0,%1,%2,%3}, [%4];"
                 : "=r"(r[0]), "=r"(r[1]), "=r"(r[2]), "=r"(r[3]) : "r"(addr));
}
__device__ __forceinline__ void mma16816(float c[4], const uint32_t a[4], const uint32_t b[2]) {
    asm volatile("mma.sync.aligned.m16n8k16.row.col.f32.bf16.bf16.f32 "
                 "{%0,%1,%2,%3}, {%4,%5,%6,%7}, {%8,%9}, {%0,%1,%2,%3};"
                 : "+f"(c[0]), "+f"(c[1]), "+f"(c[2]), "+f"(c[3])
                 : "r"(a[0]), "r"(a[1]), "r"(a[2]), "r"(a[3]), "r"(b[0]), "r"(b[1]));
}

#define APAD 40    // 32 + 8 halves  (row = 80B, 16B-aligned, conflict-free)
#define BPAD 136   // 128 + 8 halves (row = 272B)

template<int EPI>
__global__ __launch_bounds__(256)
void gemm_tc(const float* __restrict__ A, const float* __restrict__ Bm,
             const float* __restrict__ bias, const float* __restrict__ Rm,
             float* __restrict__ C, int Mn, int Nn, int Kn)
{
    __shared__ __align__(16) __nv_bfloat16 AsH[128][APAD];
    __shared__ __align__(16) __nv_bfloat16 AsL[128][APAD];
    __shared__ __align__(16) __nv_bfloat16 BsH[32][BPAD];
    __shared__ __align__(16) __nv_bfloat16 BsL[32][BPAD];

    const int tid  = threadIdx.x;
    const int lane = tid & 31;
    const int wid  = tid >> 5;
    const int bm = blockIdx.y * 128;
    const int bn = blockIdx.x * 128;
    const int wm = (wid & 1) * 64;     // warp M offset in tile
    const int wn = (wid >> 1) * 32;    // warp N offset in tile

    float acc[4][4][4];
    #pragma unroll
    for (int mi = 0; mi < 4; mi++)
        #pragma unroll
        for (int ni = 0; ni < 4; ni++)
            #pragma unroll
            for (int j = 0; j < 4; j++) acc[mi][ni][j] = 0.f;

    // global load geometry
    const int arow = tid >> 1;          // 0..127
    const int acg  = (tid & 1) * 16;    // 0 or 16
    const int brow = tid >> 3;          // 0..31
    const int bcg  = (tid & 7) * 16;    // 0..112
    const float* Ap = A  + (size_t)(bm + arow) * Kn + acg;
    const float* Bp = Bm + (size_t)brow * Nn + bn + bcg;

    // ldmatrix lane addressing
    const int lrow = lane & 7;
    const int lq1  = (lane >> 3) & 1;   // +8 rows for quads 1,3
    const int lq2  = (lane >> 4);       // +8 cols for quads 2,3

    for (int k0 = 0; k0 < Kn; k0 += 32) {
        float4 av[4], bv[4];
        #pragma unroll
        for (int i = 0; i < 4; i++) av[i] = *(const float4*)(Ap + k0 + i * 4);
        #pragma unroll
        for (int i = 0; i < 4; i++) bv[i] = *(const float4*)(Bp + (size_t)k0 * Nn + i * 4);

        __syncthreads();   // previous tile fully consumed
        #pragma unroll
        for (int i = 0; i < 4; i++) {
            float f[4] = {av[i].x, av[i].y, av[i].z, av[i].w};
            __nv_bfloat16 h[4], l[4];
            #pragma unroll
            for (int j = 0; j < 4; j++) {
                h[j] = __float2bfloat16_rn(f[j]);
                l[j] = __float2bfloat16_rn(f[j] - __bfloat162float(h[j]));
            }
            uint32_t* dH = (uint32_t*)&AsH[arow][acg + i * 4];
            uint32_t* dL = (uint32_t*)&AsL[arow][acg + i * 4];
            dH[0] = pack_bf2(h[0], h[1]); dH[1] = pack_bf2(h[2], h[3]);
            dL[0] = pack_bf2(l[0], l[1]); dL[1] = pack_bf2(l[2], l[3]);
        }
        #pragma unroll
        for (int i = 0; i < 4; i++) {
            float f[4] = {bv[i].x, bv[i].y, bv[i].z, bv[i].w};
            __nv_bfloat16 h[4], l[4];
            #pragma unroll
            for (int j = 0; j < 4; j++) {
                h[j] = __float2bfloat16_rn(f[j]);
                l[j] = __float2bfloat16_rn(f[j] - __bfloat162float(h[j]));
            }
            uint32_t* dH = (uint32_t*)&BsH[brow][bcg + i * 4];
            uint32_t* dL = (uint32_t*)&BsL[brow][bcg + i * 4];
            dH[0] = pack_bf2(h[0], h[1]); dH[1] = pack_bf2(h[2], h[3]);
            dL[0] = pack_bf2(l[0], l[1]); dL[1] = pack_bf2(l[2], l[3]);
        }
        __syncthreads();

        #pragma unroll
        for (int ks = 0; ks < 32; ks += 16) {
            uint32_t aH[4][4], aL[4][4];
            #pragma unroll
            for (int mi = 0; mi < 4; mi++) {
                int r = wm + mi * 16 + lrow + lq1 * 8;
                int c = ks + lq2 * 8;
                ldsm_x4(aH[mi], &AsH[r][c]);
                ldsm_x4(aL[mi], &AsL[r][c]);
            }
            uint32_t bH[2][4], bL[2][4];
            #pragma unroll
            for (int nj = 0; nj < 2; nj++) {
                int r = ks + lrow + lq1 * 8;
                int c = wn + nj * 16 + lq2 * 8;
                ldsm_x4_t(bH[nj], &BsH[r][c]);
                ldsm_x4_t(bL[nj], &BsL[r][c]);
            }
            #pragma unroll
            for (int mi = 0; mi < 4; mi++)
                #pragma unroll
                for (int ni = 0; ni < 4; ni++) {
                    const uint32_t* bh = &bH[ni >> 1][(ni & 1) * 2];
                    const uint32_t* bl = &bL[ni >> 1][(ni & 1) * 2];
                    mma16816(acc[mi][ni], aH[mi], bh);
                    mma16816(acc[mi][ni], aH[mi], bl);
                    mma16816(acc[mi][ni], aL[mi], bh);
                }
        }
    }

    // Epilogue. c0,c1 -> (row, 2j),(row, 2j+1); c2,c3 -> row+8.
    const int row0 = bm + wm + (lane >> 2);
    const int col0 = bn + wn + (lane & 3) * 2;
    #pragma unroll
    for (int mi = 0; mi < 4; mi++)
        #pragma unroll
        for (int ni = 0; ni < 4; ni++) {
            int m = row0 + mi * 16;
            int n = col0 + ni * 8;
            float2 bia = *(const float2*)(bias + n);
            float v0 = acc[mi][ni][0] + bia.x;
            float v1 = acc[mi][ni][1] + bia.y;
            float v2 = acc[mi][ni][2] + bia.x;
            float v3 = acc[mi][ni][3] + bia.y;
            if (EPI == 1) {
                v0 = fmaxf(v0, 0.f); v1 = fmaxf(v1, 0.f);
                v2 = fmaxf(v2, 0.f); v3 = fmaxf(v3, 0.f);
            }
            if (EPI == 2) {
                float2 r0 = *(const float2*)(Rm + (size_t)m * Nn + n);
                float2 r1 = *(const float2*)(Rm + (size_t)(m + 8) * Nn + n);
                v0 += r0.x; v1 += r0.y; v2 += r1.x; v3 += r1.y;
            }
            *(float2*)(C + (size_t)m * Nn + n)       = make_float2(v0, v1);
            *(float2*)(C + (size_t)(m + 8) * Nn + n) = make_float2(v2, v3);
        }
}

// ---------------------------------------------------------------------------
// Flash attention (fp32, online softmax). Unchanged from round 2.
// ---------------------------------------------------------------------------
#define FPAD 68
#define FTILE (64 * FPAD)

__global__ __launch_bounds__(256)
void flash_kernel(const float* __restrict__ Qg, const float* __restrict__ Kg,
                  const float* __restrict__ Vg, const int* __restrict__ mask,
                  float* __restrict__ ctx)
{
    extern __shared__ float smf[];
    float* Qs  = smf;
    float* KsT = smf + FTILE;
    float* Vs  = smf + 2 * FTILE;
    float* Ps  = smf + 3 * FTILE;
    int*   msk = (int*)(smf + 4 * FTILE);

    const int qt = blockIdx.x, h = blockIdx.y, b = blockIdx.z;
    const int tid = threadIdx.x;
    const int r  = tid >> 2;
    const int cg = (tid & 3) << 4;

    const float* Qb = Qg + ((size_t)(b * Ssz) + qt * 64 + r) * Dsz + h * HDim;
    #pragma unroll
    for (int i = 0; i < 16; i += 4)
        *(float4*)&Qs[r * FPAD + cg + i] = *(const float4*)(Qb + cg + i);

    float m_i = -1e30f, l_i = 0.f;
    float acc[16];
    #pragma unroll
    for (int j = 0; j < 16; j++) acc[j] = 0.f;

    const float invscale = 1.0f / 32.0f;

    for (int kt = 0; kt < Ssz / 64; ++kt) {
        const int k0 = kt * 64;
        const float* Kb = Kg + ((size_t)(b * Ssz) + k0 + r) * Dsz + h * HDim;
        const float* Vb = Vg + ((size_t)(b * Ssz) + k0 + r) * Dsz + h * HDim;
        __syncthreads();
        #pragma unroll
        for (int i = 0; i < 16; i++)
            KsT[(cg + i) * FPAD + r] = Kb[cg + i];
        #pragma unroll
        for (int i = 0; i < 16; i += 4)
            *(float4*)&Vs[r * FPAD + cg + i] = *(const float4*)(Vb + cg + i);
        if (tid < 64) msk[tid] = mask[b * Ssz + k0 + tid];
        __syncthreads();

        float s[16];
        #pragma unroll
        for (int j = 0; j < 16; j++) s[j] = 0.f;
        #pragma unroll 8
        for (int d = 0; d < 64; ++d) {
            float qv = Qs[r * FPAD + d];
            #pragma unroll
            for (int j = 0; j < 16; j++)
                s[j] = fmaf(qv, KsT[d * FPAD + cg + j], s[j]);
        }
        float mx = -1e30f;
        #pragma unroll
        for (int j = 0; j < 16; j++) {
            float e = s[j] * invscale;
            if (msk[cg + j] == 0) e = -1e10f;
            s[j] = e;
            mx = fmaxf(mx, e);
        }
        mx = fmaxf(mx, __shfl_xor_sync(0xffffffffu, mx, 1));
        mx = fmaxf(mx, __shfl_xor_sync(0xffffffffu, mx, 2));
        float m_new = fmaxf(m_i, mx);
        float alpha = __expf(m_i - m_new);
        float lsum = 0.f;
        #pragma unroll
        for (int j = 0; j < 16; j++) {
            float p = __expf(s[j] - m_new);
            s[j] = p;
            lsum += p;
        }
        lsum += __shfl_xor_sync(0xffffffffu, lsum, 1);
        lsum += __shfl_xor_sync(0xffffffffu, lsum, 2);
        l_i = l_i * alpha + lsum;
        m_i = m_new;
        #pragma unroll
        for (int j = 0; j < 16; j++) acc[j] *= alpha;
        #pragma unroll
        for (int j = 0; j < 16; j++) Ps[r * FPAD + cg + j] = s[j];
        __syncwarp();
        #pragma unroll 8
        for (int k = 0; k < 64; ++k) {
            float pv = Ps[r * FPAD + k];
            #pragma unroll
            for (int j = 0; j < 16; j++)
                acc[j] = fmaf(pv, Vs[k * FPAD + cg + j], acc[j]);
        }
    }
    float invl = 1.f / l_i;
    float* Ob = ctx + ((size_t)(b * Ssz) + qt * 64 + r) * Dsz + h * HDim;
    #pragma unroll
    for (int j = 0; j < 16; j++)
        Ob[cg + j] = acc[j] * invl;
}

// ---------------------------------------------------------------------------
// LayerNorm
// ---------------------------------------------------------------------------
__global__ __launch_bounds__(256)
void ln_kernel(const float* __restrict__ in, const float* __restrict__ g,
               const float* __restrict__ be, float* __restrict__ out)
{
    const int row = blockIdx.x;
    const int tid = threadIdx.x;
    const float* p = in + (size_t)row * Dsz;
    float4 v = *(const float4*)(p + tid * 4);
    float s  = v.x + v.y + v.z + v.w;
    float s2 = v.x*v.x + v.y*v.y + v.z*v.z + v.w*v.w;
    #pragma unroll
    for (int o = 16; o > 0; o >>= 1) {
        s  += __shfl_xor_sync(0xffffffffu, s,  o);
        s2 += __shfl_xor_sync(0xffffffffu, s2, o);
    }
    __shared__ float ws[8], ws2[8];
    if ((tid & 31) == 0) { ws[tid >> 5] = s; ws2[tid >> 5] = s2; }
    __syncthreads();
    if (tid < 32) {
        float a  = (tid < 8) ? ws[tid]  : 0.f;
        float a2 = (tid < 8) ? ws2[tid] : 0.f;
        #pragma unroll
        for (int o = 4; o > 0; o >>= 1) {
            a  += __shfl_xor_sync(0xffffffffu, a,  o);
            a2 += __shfl_xor_sync(0xffffffffu, a2, o);
        }
        if (tid == 0) { ws[0] = a; ws2[0] = a2; }
    }
    __syncthreads();
    float mean = ws[0] * (1.f / Dsz);
    float var  = ws2[0] * (1.f / Dsz) - mean * mean;
    float rstd = rsqrtf(var + 1e-5f);
    float4 gv = *(const float4*)(g  + tid * 4);
    float4 bv = *(const float4*)(be + tid * 4);
    float4 o;
    o.x = (v.x - mean) * rstd * gv.x + bv.x;
    o.y = (v.y - mean) * rstd * gv.y + bv.y;
    o.z = (v.z - mean) * rstd * gv.z + bv.z;
    o.w = (v.w - mean) * rstd * gv.w + bv.w;
    *(float4*)(out + (size_t)row * Dsz + tid * 4) = o;
}

// ---------------------------------------------------------------------------
// Launcher
// ---------------------------------------------------------------------------
extern "C" void kernel_launch(void* const* d_in, const int* in_sizes, int n_in,
                              void* d_out, int out_size)
{
    const int*   src  = (const int*)d_in[0];
    const int*   mask = (const int*)d_in[1];
    const float* tok  = (const float*)d_in[2];
    const float* pos  = (const float*)d_in[3];
    const float* Wq   = (const float*)d_in[4];
    const float* bq   = (const float*)d_in[5];
    const float* Wk   = (const float*)d_in[6];
    const float* bk   = (const float*)d_in[7];
    const float* Wv   = (const float*)d_in[8];
    const float* bv   = (const float*)d_in[9];
    const float* Wo   = (const float*)d_in[10];
    const float* bo   = (const float*)d_in[11];
    const float* g1   = (const float*)d_in[12];
    const float* be1  = (const float*)d_in[13];
    const float* g2   = (const float*)d_in[14];
    const float* be2  = (const float*)d_in[15];
    const float* W1   = (const float*)d_in[16];
    const float* bf1  = (const float*)d_in[17];
    const float* W2   = (const float*)d_in[18];
    const float* bf2  = (const float*)d_in[19];

    float* scratch = nullptr;
    cudaGetSymbolAddress((void**)&scratch, g_scratch);
    const size_t MD = (size_t)Msz * Dsz;
    float* x   = scratch;
    float* tmp = scratch + MD;
    float* q   = scratch + 2 * MD;
    float* k   = scratch + 3 * MD;
    float* v   = scratch + 4 * MD;
    float* ctx = scratch + 5 * MD;
    float* ff  = scratch + 6 * MD;

    const int FLASH_SMEM = 4 * FTILE * 4 + 64 * 4;
    cudaFuncSetAttribute(flash_kernel,
                         cudaFuncAttributeMaxDynamicSharedMemorySize, FLASH_SMEM);

    embed_kernel<<<(Msz * Dsz) / 256, 256>>>(src, tok, pos, x);

    dim3 g_dd(Dsz / 128, Msz / 128);   // 8 x 32
    dim3 g_df(Fsz / 128, Msz / 128);   // 32 x 32
    dim3 g_fl(Ssz / 64, Hn, Bsz);

    for (int i = 0; i < Lnum; i++) {
        const float* Wqi = Wq + (size_t)i * Dsz * Dsz;
        const float* Wki = Wk + (size_t)i * Dsz * Dsz;
        const float* Wvi = Wv + (size_t)i * Dsz * Dsz;
        const float* Woi = Wo + (size_t)i * Dsz * Dsz;
        const float* W1i = W1 + (size_t)i * Dsz * Fsz;
        const float* W2i = W2 + (size_t)i * Fsz * Dsz;
        const float* bqi = bq + (size_t)i * Dsz;
        const float* bki = bk + (size_t)i * Dsz;
        const float* bvi = bv + (size_t)i * Dsz;
        const float* boi = bo + (size_t)i * Dsz;
        const float* b1i = bf1 + (size_t)i * Fsz;
        const float* b2i = bf2 + (size_t)i * Dsz;

        gemm_tc<0><<<g_dd, 256>>>(x, Wqi, bqi, nullptr, q, Msz, Dsz, Dsz);
        gemm_tc<0><<<g_dd, 256>>>(x, Wki, bki, nullptr, k, Msz, Dsz, Dsz);
        gemm_tc<0><<<g_dd, 256>>>(x, Wvi, bvi, nullptr, v, Msz, Dsz, Dsz);

        flash_kernel<<<g_fl, 256, FLASH_SMEM>>>(q, k, v, mask, ctx);

        gemm_tc<2><<<g_dd, 256>>>(ctx, Woi, boi, x, tmp, Msz, Dsz, Dsz);
        ln_kernel<<<Msz, 256>>>(tmp, g1 + (size_t)i * Dsz, be1 + (size_t)i * Dsz, x);

        gemm_tc<1><<<g_df, 256>>>(x, W1i, b1i, nullptr, ff, Msz, Fsz, Dsz);
        gemm_tc<2><<<g_dd, 256>>>(ff, W2i, b2i, x, tmp, Msz, Dsz, Fsz);

        float* lnout = (i == Lnum - 1) ? (float*)d_out : x;
        ln_kernel<<<Msz, 256>>>(tmp, g2 + (size_t)i * Dsz, be2 + (size_t)i * Dsz, lnout);
    }
}

// round 6
// speedup vs baseline: 1.5055x; 1.0987x over previous
#include <cuda_runtime.h>
#include <cuda_bf16.h>
#include <cstdint>

// Problem constants
#define Bsz  8
#define Ssz  512
#define Dsz  1024
#define Hn   16
#define HDim 64
#define Fsz  4096
#define Lnum 6
#define Msz  (Bsz*Ssz)   // 4096 rows

__device__ float g_scratch[(size_t)Msz*Dsz*6 + (size_t)Msz*Fsz];

// ---------------------------------------------------------------------------
// Embedding
// ---------------------------------------------------------------------------
__global__ void embed_kernel(const int* __restrict__ src,
                             const float* __restrict__ tok,
                             const float* __restrict__ pos,
                             float* __restrict__ x)
{
    int i = blockIdx.x * blockDim.x + threadIdx.x;
    int m = i >> 10;
    int d = i & 1023;
    int s = m & (Ssz - 1);
    x[i] = tok[(size_t)src[m] * Dsz + d] * 32.0f + pos[s * Dsz + d];
}

// ---------------------------------------------------------------------------
// Tensor-core GEMM, split-bf16 emulation, 2-stage double-buffered pipeline.
// Single non-template kernel; epilogue selected by runtime flag (CTA-uniform).
// ---------------------------------------------------------------------------
__device__ __forceinline__ uint32_t pack_bf2(__nv_bfloat16 a, __nv_bfloat16 b) {
    return ((uint32_t)__bfloat16_as_ushort(b) << 16) | (uint32_t)__bfloat16_as_ushort(a);
}
__device__ __forceinline__ void ldsm_x4(uint32_t r[4], const void* p) {
    uint32_t addr = (uint32_t)__cvta_generic_to_shared(p);
    asm volatile("ldmatrix.sync.aligned.m8n8.x4.shared.b16 {%0,%1,%2,%3}, [%4];"
                 : "=r"(r[0]), "=r"(r[1]), "=r"(r[2]), "=r"(r[3]) : "r"(addr));
}
__device__ __forceinline__ void ldsm_x4_t(uint32_t r[4], const void* p) {
    uint32_t addr = (uint32_t)__cvta_generic_to_shared(p);
    asm volatile("ldmatrix.sync.aligned.m8n8.x4.trans.shared.b16 {%0,%1,%2,%3}, [%4];"
                 : "=r"(r[0]), "=r"(r[1]), "=r"(r[2]), "=r"(r[3]) : "r"(addr));
}
__device__ __forceinline__ void mma16816(float c[4], const uint32_t a[4], const uint32_t b[2]) {
    asm volatile("mma.sync.aligned.m16n8k16.row.col.f32.bf16.bf16.f32 "
                 "{%0,%1,%2,%3}, {%4,%5,%6,%7}, {%8,%9}, {%0,%1,%2,%3};"
                 : "+f"(c[0]), "+f"(c[1]), "+f"(c[2]), "+f"(c[3])
                 : "r"(a[0]), "r"(a[1]), "r"(a[2]), "r"(a[3]), "r"(b[0]), "r"(b[1]));
}

#define APAD 40    // halves per A row (80 B, 16B-aligned, ldsm conflict-free)
#define BPAD 136   // halves per B row (272 B)
#define A_HALVES (128 * APAD)   // 5120
#define B_HALVES (32 * BPAD)    // 4352
#define STG_HALVES (2 * A_HALVES + 2 * B_HALVES)   // 18944
#define GEMM_SMEM (2 * STG_HALVES * 2)             // bytes = 75776

// Convert one 16-float fragment pair (A row seg + B row seg) into hi/lo smem.
__device__ __forceinline__ void cvt_store_tile(
    __nv_bfloat16* stg, const float4 av[4], const float4 bv[4],
    int arow, int acg, int brow, int bcg)
{
    __nv_bfloat16* AsH = stg;
    __nv_bfloat16* AsL = AsH + A_HALVES;
    __nv_bfloat16* BsH = AsL + A_HALVES;
    __nv_bfloat16* BsL = BsH + B_HALVES;
    #pragma unroll
    for (int i = 0; i < 4; i++) {
        float f[4] = {av[i].x, av[i].y, av[i].z, av[i].w};
        __nv_bfloat16 h[4], l[4];
        #pragma unroll
        for (int j = 0; j < 4; j++) {
            h[j] = __float2bfloat16_rn(f[j]);
            l[j] = __float2bfloat16_rn(f[j] - __bfloat162float(h[j]));
        }
        uint32_t* dH = (uint32_t*)(AsH + arow * APAD + acg + i * 4);
        uint32_t* dL = (uint32_t*)(AsL + arow * APAD + acg + i * 4);
        dH[0] = pack_bf2(h[0], h[1]); dH[1] = pack_bf2(h[2], h[3]);
        dL[0] = pack_bf2(l[0], l[1]); dL[1] = pack_bf2(l[2], l[3]);
    }
    #pragma unroll
    for (int i = 0; i < 4; i++) {
        float f[4] = {bv[i].x, bv[i].y, bv[i].z, bv[i].w};
        __nv_bfloat16 h[4], l[4];
        #pragma unroll
        for (int j = 0; j < 4; j++) {
            h[j] = __float2bfloat16_rn(f[j]);
            l[j] = __float2bfloat16_rn(f[j] - __bfloat162float(h[j]));
        }
        uint32_t* dH = (uint32_t*)(BsH + brow * BPAD + bcg + i * 4);
        uint32_t* dL = (uint32_t*)(BsL + brow * BPAD + bcg + i * 4);
        dH[0] = pack_bf2(h[0], h[1]); dH[1] = pack_bf2(h[2], h[3]);
        dL[0] = pack_bf2(l[0], l[1]); dL[1] = pack_bf2(l[2], l[3]);
    }
}

__device__ __forceinline__ void compute_tile(
    float acc[4][4][4], const __nv_bfloat16* stg,
    int wm, int wn, int lrow, int lq1, int lq2)
{
    const __nv_bfloat16* AsH = stg;
    const __nv_bfloat16* AsL = AsH + A_HALVES;
    const __nv_bfloat16* BsH = AsL + A_HALVES;
    const __nv_bfloat16* BsL = BsH + B_HALVES;
    #pragma unroll
    for (int ks = 0; ks < 32; ks += 16) {
        uint32_t aH[4][4], aL[4][4];
        #pragma unroll
        for (int mi = 0; mi < 4; mi++) {
            int r = wm + mi * 16 + lrow + lq1 * 8;
            int c = ks + lq2 * 8;
            ldsm_x4(aH[mi], AsH + r * APAD + c);
            ldsm_x4(aL[mi], AsL + r * APAD + c);
        }
        uint32_t bH[2][4], bL[2][4];
        #pragma unroll
        for (int nj = 0; nj < 2; nj++) {
            int r = ks + lrow + lq1 * 8;
            int c = wn + nj * 16 + lq2 * 8;
            ldsm_x4_t(bH[nj], BsH + r * BPAD + c);
            ldsm_x4_t(bL[nj], BsL + r * BPAD + c);
        }
        #pragma unroll
        for (int mi = 0; mi < 4; mi++)
            #pragma unroll
            for (int ni = 0; ni < 4; ni++) {
                const uint32_t* bh = &bH[ni >> 1][(ni & 1) * 2];
                const uint32_t* bl = &bL[ni >> 1][(ni & 1) * 2];
                mma16816(acc[mi][ni], aH[mi], bh);
                mma16816(acc[mi][ni], aH[mi], bl);
                mma16816(acc[mi][ni], aL[mi], bh);
            }
    }
}

__global__ __launch_bounds__(256)
void gemm_tc(const float* __restrict__ A, const float* __restrict__ Bm,
             const float* __restrict__ bias, const float* __restrict__ Rm,
             float* __restrict__ C, int Nn, int Kn, int epi)
{
    extern __shared__ __align__(16) __nv_bfloat16 sm[];

    const int tid  = threadIdx.x;
    const int lane = tid & 31;
    const int wid  = tid >> 5;
    const int bm = blockIdx.y * 128;
    const int bn = blockIdx.x * 128;
    const int wm = (wid & 1) * 64;
    const int wn = (wid >> 1) * 32;

    float acc[4][4][4];
    #pragma unroll
    for (int mi = 0; mi < 4; mi++)
        #pragma unroll
        for (int ni = 0; ni < 4; ni++)
            #pragma unroll
            for (int j = 0; j < 4; j++) acc[mi][ni][j] = 0.f;

    const int arow = tid >> 1;
    const int acg  = (tid & 1) * 16;
    const int brow = tid >> 3;
    const int bcg  = (tid & 7) * 16;
    const float* Ap = A  + (size_t)(bm + arow) * Kn + acg;
    const float* Bp = Bm + (size_t)brow * Nn + bn + bcg;

    const int lrow = lane & 7;
    const int lq1  = (lane >> 3) & 1;
    const int lq2  = (lane >> 4);

    float4 av[4], bv[4];

    // Prologue: tile 0 into stage 0
    #pragma unroll
    for (int i = 0; i < 4; i++) av[i] = *(const float4*)(Ap + i * 4);
    #pragma unroll
    for (int i = 0; i < 4; i++) bv[i] = *(const float4*)(Bp + i * 4);
    cvt_store_tile(sm, av, bv, arow, acg, brow, bcg);
    __syncthreads();

    const int nk = Kn / 32;
    #pragma unroll 1
    for (int it = 0; it < nk; it++) {
        const int p = it & 1;
        const bool more = (it + 1 < nk);
        if (more) {
            const int k0 = (it + 1) * 32;
            #pragma unroll
            for (int i = 0; i < 4; i++) av[i] = *(const float4*)(Ap + k0 + i * 4);
            #pragma unroll
            for (int i = 0; i < 4; i++) bv[i] = *(const float4*)(Bp + (size_t)k0 * Nn + i * 4);
        }
        compute_tile(acc, sm + p * STG_HALVES, wm, wn, lrow, lq1, lq2);
        if (more) {
            cvt_store_tile(sm + (p ^ 1) * STG_HALVES, av, bv, arow, acg, brow, bcg);
            __syncthreads();
        }
    }

    // Epilogue (epi: 0 = bias, 1 = bias+relu, 2 = bias+residual)
    const int row0 = bm + wm + (lane >> 2);
    const int col0 = bn + wn + (lane & 3) * 2;
    #pragma unroll
    for (int mi = 0; mi < 4; mi++)
        #pragma unroll
        for (int ni = 0; ni < 4; ni++) {
            int m = row0 + mi * 16;
            int n = col0 + ni * 8;
            float2 bia = *(const float2*)(bias + n);
            float v0 = acc[mi][ni][0] + bia.x;
            float v1 = acc[mi][ni][1] + bia.y;
            float v2 = acc[mi][ni][2] + bia.x;
            float v3 = acc[mi][ni][3] + bia.y;
            if (epi == 1) {
                v0 = fmaxf(v0, 0.f); v1 = fmaxf(v1, 0.f);
                v2 = fmaxf(v2, 0.f); v3 = fmaxf(v3, 0.f);
            } else if (epi == 2) {
                float2 r0 = *(const float2*)(Rm + (size_t)m * Nn + n);
                float2 r1 = *(const float2*)(Rm + (size_t)(m + 8) * Nn + n);
                v0 += r0.x; v1 += r0.y; v2 += r1.x; v3 += r1.y;
            }
            *(float2*)(C + (size_t)m * Nn + n)       = make_float2(v0, v1);
            *(float2*)(C + (size_t)(m + 8) * Nn + n) = make_float2(v2, v3);
        }
}

// ---------------------------------------------------------------------------
// Flash attention (fp32, online softmax). Unchanged.
// ---------------------------------------------------------------------------
#define FPAD 68
#define FTILE (64 * FPAD)

__global__ __launch_bounds__(256)
void flash_kernel(const float* __restrict__ Qg, const float* __restrict__ Kg,
                  const float* __restrict__ Vg, const int* __restrict__ mask,
                  float* __restrict__ ctx)
{
    extern __shared__ float smf[];
    float* Qs  = smf;
    float* KsT = smf + FTILE;
    float* Vs  = smf + 2 * FTILE;
    float* Ps  = smf + 3 * FTILE;
    int*   msk = (int*)(smf + 4 * FTILE);

    const int qt = blockIdx.x, h = blockIdx.y, b = blockIdx.z;
    const int tid = threadIdx.x;
    const int r  = tid >> 2;
    const int cg = (tid & 3) << 4;

    const float* Qb = Qg + ((size_t)(b * Ssz) + qt * 64 + r) * Dsz + h * HDim;
    #pragma unroll
    for (int i = 0; i < 16; i += 4)
        *(float4*)&Qs[r * FPAD + cg + i] = *(const float4*)(Qb + cg + i);

    float m_i = -1e30f, l_i = 0.f;
    float acc[16];
    #pragma unroll
    for (int j = 0; j < 16; j++) acc[j] = 0.f;

    const float invscale = 1.0f / 32.0f;

    for (int kt = 0; kt < Ssz / 64; ++kt) {
        const int k0 = kt * 64;
        const float* Kb = Kg + ((size_t)(b * Ssz) + k0 + r) * Dsz + h * HDim;
        const float* Vb = Vg + ((size_t)(b * Ssz) + k0 + r) * Dsz + h * HDim;
        __syncthreads();
        #pragma unroll
        for (int i = 0; i < 16; i++)
            KsT[(cg + i) * FPAD + r] = Kb[cg + i];
        #pragma unroll
        for (int i = 0; i < 16; i += 4)
            *(float4*)&Vs[r * FPAD + cg + i] = *(const float4*)(Vb + cg + i);
        if (tid < 64) msk[tid] = mask[b * Ssz + k0 + tid];
        __syncthreads();

        float s[16];
        #pragma unroll
        for (int j = 0; j < 16; j++) s[j] = 0.f;
        #pragma unroll 8
        for (int d = 0; d < 64; ++d) {
            float qv = Qs[r * FPAD + d];
            #pragma unroll
            for (int j = 0; j < 16; j++)
                s[j] = fmaf(qv, KsT[d * FPAD + cg + j], s[j]);
        }
        float mx = -1e30f;
        #pragma unroll
        for (int j = 0; j < 16; j++) {
            float e = s[j] * invscale;
            if (msk[cg + j] == 0) e = -1e10f;
            s[j] = e;
            mx = fmaxf(mx, e);
        }
        mx = fmaxf(mx, __shfl_xor_sync(0xffffffffu, mx, 1));
        mx = fmaxf(mx, __shfl_xor_sync(0xffffffffu, mx, 2));
        float m_new = fmaxf(m_i, mx);
        float alpha = __expf(m_i - m_new);
        float lsum = 0.f;
        #pragma unroll
        for (int j = 0; j < 16; j++) {
            float p = __expf(s[j] - m_new);
            s[j] = p;
            lsum += p;
        }
        lsum += __shfl_xor_sync(0xffffffffu, lsum, 1);
        lsum += __shfl_xor_sync(0xffffffffu, lsum, 2);
        l_i = l_i * alpha + lsum;
        m_i = m_new;
        #pragma unroll
        for (int j = 0; j < 16; j++) acc[j] *= alpha;
        #pragma unroll
        for (int j = 0; j < 16; j++) Ps[r * FPAD + cg + j] = s[j];
        __syncwarp();
        #pragma unroll 8
        for (int k = 0; k < 64; ++k) {
            float pv = Ps[r * FPAD + k];
            #pragma unroll
            for (int j = 0; j < 16; j++)
                acc[j] = fmaf(pv, Vs[k * FPAD + cg + j], acc[j]);
        }
    }
    float invl = 1.f / l_i;
    float* Ob = ctx + ((size_t)(b * Ssz) + qt * 64 + r) * Dsz + h * HDim;
    #pragma unroll
    for (int j = 0; j < 16; j++)
        Ob[cg + j] = acc[j] * invl;
}

// ---------------------------------------------------------------------------
// LayerNorm
// ---------------------------------------------------------------------------
__global__ __launch_bounds__(256)
void ln_kernel(const float* __restrict__ in, const float* __restrict__ g,
               const float* __restrict__ be, float* __restrict__ out)
{
    const int row = blockIdx.x;
    const int tid = threadIdx.x;
    const float* p = in + (size_t)row * Dsz;
    float4 v = *(const float4*)(p + tid * 4);
    float s  = v.x + v.y + v.z + v.w;
    float s2 = v.x*v.x + v.y*v.y + v.z*v.z + v.w*v.w;
    #pragma unroll
    for (int o = 16; o > 0; o >>= 1) {
        s  += __shfl_xor_sync(0xffffffffu, s,  o);
        s2 += __shfl_xor_sync(0xffffffffu, s2, o);
    }
    __shared__ float ws[8], ws2[8];
    if ((tid & 31) == 0) { ws[tid >> 5] = s; ws2[tid >> 5] = s2; }
    __syncthreads();
    if (tid < 32) {
        float a  = (tid < 8) ? ws[tid]  : 0.f;
        float a2 = (tid < 8) ? ws2[tid] : 0.f;
        #pragma unroll
        for (int o = 4; o > 0; o >>= 1) {
            a  += __shfl_xor_sync(0xffffffffu, a,  o);
            a2 += __shfl_xor_sync(0xffffffffu, a2, o);
        }
        if (tid == 0) { ws[0] = a; ws2[0] = a2; }
    }
    __syncthreads();
    float mean = ws[0] * (1.f / Dsz);
    float var  = ws2[0] * (1.f / Dsz) - mean * mean;
    float rstd = rsqrtf(var + 1e-5f);
    float4 gv = *(const float4*)(g  + tid * 4);
    float4 bv = *(const float4*)(be + tid * 4);
    float4 o;
    o.x = (v.x - mean) * rstd * gv.x + bv.x;
    o.y = (v.y - mean) * rstd * gv.y + bv.y;
    o.z = (v.z - mean) * rstd * gv.z + bv.z;
    o.w = (v.w - mean) * rstd * gv.w + bv.w;
    *(float4*)(out + (size_t)row * Dsz + tid * 4) = o;
}

// ---------------------------------------------------------------------------
// Launcher
// ---------------------------------------------------------------------------
extern "C" void kernel_launch(void* const* d_in, const int* in_sizes, int n_in,
                              void* d_out, int out_size)
{
    const int*   src  = (const int*)d_in[0];
    const int*   mask = (const int*)d_in[1];
    const float* tok  = (const float*)d_in[2];
    const float* pos  = (const float*)d_in[3];
    const float* Wq   = (const float*)d_in[4];
    const float* bq   = (const float*)d_in[5];
    const float* Wk   = (const float*)d_in[6];
    const float* bk   = (const float*)d_in[7];
    const float* Wv   = (const float*)d_in[8];
    const float* bv   = (const float*)d_in[9];
    const float* Wo   = (const float*)d_in[10];
    const float* bo   = (const float*)d_in[11];
    const float* g1   = (const float*)d_in[12];
    const float* be1  = (const float*)d_in[13];
    const float* g2   = (const float*)d_in[14];
    const float* be2  = (const float*)d_in[15];
    const float* W1   = (const float*)d_in[16];
    const float* bf1  = (const float*)d_in[17];
    const float* W2   = (const float*)d_in[18];
    const float* bf2  = (const float*)d_in[19];

    float* scratch = nullptr;
    cudaGetSymbolAddress((void**)&scratch, g_scratch);
    const size_t MD = (size_t)Msz * Dsz;
    float* x   = scratch;
    float* tmp = scratch + MD;
    float* q   = scratch + 2 * MD;
    float* k   = scratch + 3 * MD;
    float* v   = scratch + 4 * MD;
    float* ctx = scratch + 5 * MD;
    float* ff  = scratch + 6 * MD;

    const int FLASH_SMEM = 4 * FTILE * 4 + 64 * 4;
    cudaFuncSetAttribute(flash_kernel,
                         cudaFuncAttributeMaxDynamicSharedMemorySize, FLASH_SMEM);
    cudaFuncSetAttribute(gemm_tc,
                         cudaFuncAttributeMaxDynamicSharedMemorySize, GEMM_SMEM);

    embed_kernel<<<(Msz * Dsz) / 256, 256>>>(src, tok, pos, x);

    dim3 g_dd(Dsz / 128, Msz / 128);   // 8 x 32
    dim3 g_df(Fsz / 128, Msz / 128);   // 32 x 32
    dim3 g_fl(Ssz / 64, Hn, Bsz);

    for (int i = 0; i < Lnum; i++) {
        const float* Wqi = Wq + (size_t)i * Dsz * Dsz;
        const float* Wki = Wk + (size_t)i * Dsz * Dsz;
        const float* Wvi = Wv + (size_t)i * Dsz * Dsz;
        const float* Woi = Wo + (size_t)i * Dsz * Dsz;
        const float* W1i = W1 + (size_t)i * Dsz * Fsz;
        const float* W2i = W2 + (size_t)i * Fsz * Dsz;
        const float* bqi = bq + (size_t)i * Dsz;
        const float* bki = bk + (size_t)i * Dsz;
        const float* bvi = bv + (size_t)i * Dsz;
        const float* boi = bo + (size_t)i * Dsz;
        const float* b1i = bf1 + (size_t)i * Fsz;
        const float* b2i = bf2 + (size_t)i * Dsz;

        gemm_tc<<<g_dd, 256, GEMM_SMEM>>>(x, Wqi, bqi, nullptr, q, Dsz, Dsz, 0);
        gemm_tc<<<g_dd, 256, GEMM_SMEM>>>(x, Wki, bki, nullptr, k, Dsz, Dsz, 0);
        gemm_tc<<<g_dd, 256, GEMM_SMEM>>>(x, Wvi, bvi, nullptr, v, Dsz, Dsz, 0);

        flash_kernel<<<g_fl, 256, FLASH_SMEM>>>(q, k, v, mask, ctx);

        gemm_tc<<<g_dd, 256, GEMM_SMEM>>>(ctx, Woi, boi, x, tmp, Dsz, Dsz, 2);
        ln_kernel<<<Msz, 256>>>(tmp, g1 + (size_t)i * Dsz, be1 + (size_t)i * Dsz, x);

        gemm_tc<<<g_df, 256, GEMM_SMEM>>>(x, W1i, b1i, nullptr, ff, Fsz, Dsz, 1);
        gemm_tc<<<g_dd, 256, GEMM_SMEM>>>(ff, W2i, b2i, x, tmp, Dsz, Fsz, 2);

        float* lnout = (i == Lnum - 1) ? (float*)d_out : x;
        ln_kernel<<<Msz, 256>>>(tmp, g2 + (size_t)i * Dsz, be2 + (size_t)i * Dsz, lnout);
    }
}

// round 7
// speedup vs baseline: 1.8261x; 1.2129x over previous
#include <cuda_runtime.h>
#include <cuda_bf16.h>
#include <cstdint>

// Problem constants
#define Bsz  8
#define Ssz  512
#define Dsz  1024
#define Hn   16
#define HDim 64
#define Fsz  4096
#define Lnum 6
#define Msz  (Bsz*Ssz)   // 4096 rows

__device__ float g_scratch[(size_t)Msz*Dsz*6 + (size_t)Msz*Fsz];
// Split (hi/lo) staging: A side up to M*F elems, B side up to D*F elems.
__device__ __nv_bfloat16 g_AH[(size_t)Msz*Fsz];
__device__ __nv_bfloat16 g_AL[(size_t)Msz*Fsz];
__device__ __nv_bfloat16 g_BH[(size_t)Dsz*Fsz];
__device__ __nv_bfloat16 g_BL[(size_t)Dsz*Fsz];

// ---------------------------------------------------------------------------
// Embedding
// ---------------------------------------------------------------------------
__global__ void embed_kernel(const int* __restrict__ src,
                             const float* __restrict__ tok,
                             const float* __restrict__ pos,
                             float* __restrict__ x)
{
    int i = blockIdx.x * blockDim.x + threadIdx.x;
    int m = i >> 10;
    int d = i & 1023;
    int s = m & (Ssz - 1);
    x[i] = tok[(size_t)src[m] * Dsz + d] * 32.0f + pos[s * Dsz + d];
}

// ---------------------------------------------------------------------------
// Split fp32 -> bf16 hi + bf16 lo (grid-stride, float4 vectorized)
// ---------------------------------------------------------------------------
__device__ __forceinline__ uint32_t pack_bf2(__nv_bfloat16 a, __nv_bfloat16 b) {
    return ((uint32_t)__bfloat16_as_ushort(b) << 16) | (uint32_t)__bfloat16_as_ushort(a);
}

__global__ __launch_bounds__(256)
void split_kernel(const float* __restrict__ in,
                  __nv_bfloat16* __restrict__ hi,
                  __nv_bfloat16* __restrict__ lo, int n4)
{
    int i = blockIdx.x * blockDim.x + threadIdx.x;
    if (i >= n4) return;
    float4 v = ((const float4*)in)[i];
    float f[4] = {v.x, v.y, v.z, v.w};
    __nv_bfloat16 h[4], l[4];
    #pragma unroll
    for (int j = 0; j < 4; j++) {
        h[j] = __float2bfloat16_rn(f[j]);
        l[j] = __float2bfloat16_rn(f[j] - __bfloat162float(h[j]));
    }
    ((uint2*)hi)[i] = make_uint2(pack_bf2(h[0], h[1]), pack_bf2(h[2], h[3]));
    ((uint2*)lo)[i] = make_uint2(pack_bf2(l[0], l[1]), pack_bf2(l[2], l[3]));
}

// ---------------------------------------------------------------------------
// Tensor-core GEMM on pre-split bf16 hi/lo, 4-stage cp.async pipeline.
// C = A@B (fp32-emulated: AhBh + AhBl + AlBh) + bias (+relu | +residual)
// Tile 128x128, BK=32, 256 threads, warp 64x32.
// ---------------------------------------------------------------------------
__device__ __forceinline__ void ldsm_x4(uint32_t r[4], const void* p) {
    uint32_t addr = (uint32_t)__cvta_generic_to_shared(p);
    asm volatile("ldmatrix.sync.aligned.m8n8.x4.shared.b16 {%0,%1,%2,%3}, [%4];"
                 : "=r"(r[0]), "=r"(r[1]), "=r"(r[2]), "=r"(r[3]) : "r"(addr));
}
__device__ __forceinline__ void ldsm_x4_t(uint32_t r[4], const void* p) {
    uint32_t addr = (uint32_t)__cvta_generic_to_shared(p);
    asm volatile("ldmatrix.sync.aligned.m8n8.x4.trans.shared.b16 {%0,%1,%2,%3}, [%4];"
                 : "=r"(r[0]), "=r"(r[1]), "=r"(r[2]), "=r"(r[3]) : "r"(addr));
}
__device__ __forceinline__ void mma16816(float c[4], const uint32_t a[4], const uint32_t b[2]) {
    asm volatile("mma.sync.aligned.m16n8k16.row.col.f32.bf16.bf16.f32 "
                 "{%0,%1,%2,%3}, {%4,%5,%6,%7}, {%8,%9}, {%0,%1,%2,%3};"
                 : "+f"(c[0]), "+f"(c[1]), "+f"(c[2]), "+f"(c[3])
                 : "r"(a[0]), "r"(a[1]), "r"(a[2]), "r"(a[3]), "r"(b[0]), "r"(b[1]));
}
__device__ __forceinline__ void cp16(void* dst_smem, const void* src) {
    uint32_t addr = (uint32_t)__cvta_generic_to_shared(dst_smem);
    asm volatile("cp.async.ca.shared.global [%0], [%1], 16;" :: "r"(addr), "l"(src));
}

#define APAD 40    // halves per A row (80 B)
#define BPAD 136   // halves per B row (272 B)
#define A_HALVES (128 * APAD)   // 5120
#define B_HALVES (32 * BPAD)    // 4352
#define STG_HALVES (2 * A_HALVES + 2 * B_HALVES)   // 18944
#define NSTG 4
#define GEMM_SMEM (NSTG * STG_HALVES * 2)          // 151552 B

__device__ __forceinline__ void issue_loads(
    __nv_bfloat16* stg,
    const __nv_bfloat16* AHg, const __nv_bfloat16* ALg,
    const __nv_bfloat16* BHg, const __nv_bfloat16* BLg,
    int tid, int bm, int bn, int k0, int Nn, int Kn)
{
    __nv_bfloat16* AsH = stg;
    __nv_bfloat16* AsL = AsH + A_HALVES;
    __nv_bfloat16* BsH = AsL + A_HALVES;
    __nv_bfloat16* BsL = BsH + B_HALVES;
    #pragma unroll
    for (int q = 0; q < 2; q++) {
        int idx = tid + q * 256;               // 0..511
        int ar = idx >> 2, ac = (idx & 3) * 8; // A: 128 rows x 4 chunks
        size_t asrc = (size_t)(bm + ar) * Kn + k0 + ac;
        cp16(AsH + ar * APAD + ac, AHg + asrc);
        cp16(AsL + ar * APAD + ac, ALg + asrc);
        int br = idx >> 4, bc = (idx & 15) * 8; // B: 32 rows x 16 chunks
        size_t bsrc = (size_t)(k0 + br) * Nn + bn + bc;
        cp16(BsH + br * BPAD + bc, BHg + bsrc);
        cp16(BsL + br * BPAD + bc, BLg + bsrc);
    }
}

__device__ __forceinline__ void compute_tile(
    float acc[4][4][4], const __nv_bfloat16* stg,
    int wm, int wn, int lrow, int lq1, int lq2)
{
    const __nv_bfloat16* AsH = stg;
    const __nv_bfloat16* AsL = AsH + A_HALVES;
    const __nv_bfloat16* BsH = AsL + A_HALVES;
    const __nv_bfloat16* BsL = BsH + B_HALVES;
    #pragma unroll
    for (int ks = 0; ks < 32; ks += 16) {
        uint32_t aH[4][4], aL[4][4];
        #pragma unroll
        for (int mi = 0; mi < 4; mi++) {
            int r = wm + mi * 16 + lrow + lq1 * 8;
            int c = ks + lq2 * 8;
            ldsm_x4(aH[mi], AsH + r * APAD + c);
            ldsm_x4(aL[mi], AsL + r * APAD + c);
        }
        uint32_t bH[2][4], bL[2][4];
        #pragma unroll
        for (int nj = 0; nj < 2; nj++) {
            int r = ks + lrow + lq1 * 8;
            int c = wn + nj * 16 + lq2 * 8;
            ldsm_x4_t(bH[nj], BsH + r * BPAD + c);
            ldsm_x4_t(bL[nj], BsL + r * BPAD + c);
        }
        #pragma unroll
        for (int mi = 0; mi < 4; mi++)
            #pragma unroll
            for (int ni = 0; ni < 4; ni++) {
                const uint32_t* bh = &bH[ni >> 1][(ni & 1) * 2];
                const uint32_t* bl = &bL[ni >> 1][(ni & 1) * 2];
                mma16816(acc[mi][ni], aH[mi], bh);
                mma16816(acc[mi][ni], aH[mi], bl);
                mma16816(acc[mi][ni], aL[mi], bh);
            }
    }
}

__global__ __launch_bounds__(256)
void gemm_tc(const __nv_bfloat16* __restrict__ AHg, const __nv_bfloat16* __restrict__ ALg,
             const __nv_bfloat16* __restrict__ BHg, const __nv_bfloat16* __restrict__ BLg,
             const float* __restrict__ bias, const float* __restrict__ Rm,
             float* __restrict__ C, int Nn, int Kn, int epi)
{
    extern __shared__ __align__(16) __nv_bfloat16 sm[];

    const int tid  = threadIdx.x;
    const int lane = tid & 31;
    const int wid  = tid >> 5;
    const int bm = blockIdx.y * 128;
    const int bn = blockIdx.x * 128;
    const int wm = (wid & 1) * 64;
    const int wn = (wid >> 1) * 32;

    float acc[4][4][4];
    #pragma unroll
    for (int mi = 0; mi < 4; mi++)
        #pragma unroll
        for (int ni = 0; ni < 4; ni++)
            #pragma unroll
            for (int j = 0; j < 4; j++) acc[mi][ni][j] = 0.f;

    const int lrow = lane & 7;
    const int lq1  = (lane >> 3) & 1;
    const int lq2  = (lane >> 4);

    const int nk = Kn / 32;

    // Prologue: prefetch first NSTG-1 stages
    #pragma unroll
    for (int s = 0; s < NSTG - 1; s++) {
        if (s < nk)
            issue_loads(sm + s * STG_HALVES, AHg, ALg, BHg, BLg,
                        tid, bm, bn, s * 32, Nn, Kn);
        asm volatile("cp.async.commit_group;" ::: "memory");
    }

    #pragma unroll 1
    for (int it = 0; it < nk; it++) {
        asm volatile("cp.async.wait_group %0;" :: "n"(NSTG - 2) : "memory");
        __syncthreads();
        compute_tile(acc, sm + (it % NSTG) * STG_HALVES, wm, wn, lrow, lq1, lq2);
        if (it + NSTG - 1 < nk)
            issue_loads(sm + ((it + NSTG - 1) % NSTG) * STG_HALVES, AHg, ALg, BHg, BLg,
                        tid, bm, bn, (it + NSTG - 1) * 32, Nn, Kn);
        asm volatile("cp.async.commit_group;" ::: "memory");
    }

    // Epilogue (epi: 0 = bias, 1 = bias+relu, 2 = bias+residual)
    const int row0 = bm + wm + (lane >> 2);
    const int col0 = bn + wn + (lane & 3) * 2;
    #pragma unroll
    for (int mi = 0; mi < 4; mi++)
        #pragma unroll
        for (int ni = 0; ni < 4; ni++) {
            int m = row0 + mi * 16;
            int n = col0 + ni * 8;
            float2 bia = *(const float2*)(bias + n);
            float v0 = acc[mi][ni][0] + bia.x;
            float v1 = acc[mi][ni][1] + bia.y;
            float v2 = acc[mi][ni][2] + bia.x;
            float v3 = acc[mi][ni][3] + bia.y;
            if (epi == 1) {
                v0 = fmaxf(v0, 0.f); v1 = fmaxf(v1, 0.f);
                v2 = fmaxf(v2, 0.f); v3 = fmaxf(v3, 0.f);
            } else if (epi == 2) {
                float2 r0 = *(const float2*)(Rm + (size_t)m * Nn + n);
                float2 r1 = *(const float2*)(Rm + (size_t)(m + 8) * Nn + n);
                v0 += r0.x; v1 += r0.y; v2 += r1.x; v3 += r1.y;
            }
            *(float2*)(C + (size_t)m * Nn + n)       = make_float2(v0, v1);
            *(float2*)(C + (size_t)(m + 8) * Nn + n) = make_float2(v2, v3);
        }
}

// ---------------------------------------------------------------------------
// Flash attention (fp32, online softmax). Unchanged.
// ---------------------------------------------------------------------------
#define FPAD 68
#define FTILE (64 * FPAD)

__global__ __launch_bounds__(256)
void flash_kernel(const float* __restrict__ Qg, const float* __restrict__ Kg,
                  const float* __restrict__ Vg, const int* __restrict__ mask,
                  float* __restrict__ ctx)
{
    extern __shared__ float smf[];
    float* Qs  = smf;
    float* KsT = smf + FTILE;
    float* Vs  = smf + 2 * FTILE;
    float* Ps  = smf + 3 * FTILE;
    int*   msk = (int*)(smf + 4 * FTILE);

    const int qt = blockIdx.x, h = blockIdx.y, b = blockIdx.z;
    const int tid = threadIdx.x;
    const int r  = tid >> 2;
    const int cg = (tid & 3) << 4;

    const float* Qb = Qg + ((size_t)(b * Ssz) + qt * 64 + r) * Dsz + h * HDim;
    #pragma unroll
    for (int i = 0; i < 16; i += 4)
        *(float4*)&Qs[r * FPAD + cg + i] = *(const float4*)(Qb + cg + i);

    float m_i = -1e30f, l_i = 0.f;
    float acc[16];
    #pragma unroll
    for (int j = 0; j < 16; j++) acc[j] = 0.f;

    const float invscale = 1.0f / 32.0f;

    for (int kt = 0; kt < Ssz / 64; ++kt) {
        const int k0 = kt * 64;
        const float* Kb = Kg + ((size_t)(b * Ssz) + k0 + r) * Dsz + h * HDim;
        const float* Vb = Vg + ((size_t)(b * Ssz) + k0 + r) * Dsz + h * HDim;
        __syncthreads();
        #pragma unroll
        for (int i = 0; i < 16; i++)
            KsT[(cg + i) * FPAD + r] = Kb[cg + i];
        #pragma unroll
        for (int i = 0; i < 16; i += 4)
            *(float4*)&Vs[r * FPAD + cg + i] = *(const float4*)(Vb + cg + i);
        if (tid < 64) msk[tid] = mask[b * Ssz + k0 + tid];
        __syncthreads();

        float s[16];
        #pragma unroll
        for (int j = 0; j < 16; j++) s[j] = 0.f;
        #pragma unroll 8
        for (int d = 0; d < 64; ++d) {
            float qv = Qs[r * FPAD + d];
            #pragma unroll
            for (int j = 0; j < 16; j++)
                s[j] = fmaf(qv, KsT[d * FPAD + cg + j], s[j]);
        }
        float mx = -1e30f;
        #pragma unroll
        for (int j = 0; j < 16; j++) {
            float e = s[j] * invscale;
            if (msk[cg + j] == 0) e = -1e10f;
            s[j] = e;
            mx = fmaxf(mx, e);
        }
        mx = fmaxf(mx, __shfl_xor_sync(0xffffffffu, mx, 1));
        mx = fmaxf(mx, __shfl_xor_sync(0xffffffffu, mx, 2));
        float m_new = fmaxf(m_i, mx);
        float alpha = __expf(m_i - m_new);
        float lsum = 0.f;
        #pragma unroll
        for (int j = 0; j < 16; j++) {
            float p = __expf(s[j] - m_new);
            s[j] = p;
            lsum += p;
        }
        lsum += __shfl_xor_sync(0xffffffffu, lsum, 1);
        lsum += __shfl_xor_sync(0xffffffffu, lsum, 2);
        l_i = l_i * alpha + lsum;
        m_i = m_new;
        #pragma unroll
        for (int j = 0; j < 16; j++) acc[j] *= alpha;
        #pragma unroll
        for (int j = 0; j < 16; j++) Ps[r * FPAD + cg + j] = s[j];
        __syncwarp();
        #pragma unroll 8
        for (int k = 0; k < 64; ++k) {
            float pv = Ps[r * FPAD + k];
            #pragma unroll
            for (int j = 0; j < 16; j++)
                acc[j] = fmaf(pv, Vs[k * FPAD + cg + j], acc[j]);
        }
    }
    float invl = 1.f / l_i;
    float* Ob = ctx + ((size_t)(b * Ssz) + qt * 64 + r) * Dsz + h * HDim;
    #pragma unroll
    for (int j = 0; j < 16; j++)
        Ob[cg + j] = acc[j] * invl;
}

// ---------------------------------------------------------------------------
// LayerNorm
// ---------------------------------------------------------------------------
__global__ __launch_bounds__(256)
void ln_kernel(const float* __restrict__ in, const float* __restrict__ g,
               const float* __restrict__ be, float* __restrict__ out)
{
    const int row = blockIdx.x;
    const int tid = threadIdx.x;
    const float* p = in + (size_t)row * Dsz;
    float4 v = *(const float4*)(p + tid * 4);
    float s  = v.x + v.y + v.z + v.w;
    float s2 = v.x*v.x + v.y*v.y + v.z*v.z + v.w*v.w;
    #pragma unroll
    for (int o = 16; o > 0; o >>= 1) {
        s  += __shfl_xor_sync(0xffffffffu, s,  o);
        s2 += __shfl_xor_sync(0xffffffffu, s2, o);
    }
    __shared__ float ws[8], ws2[8];
    if ((tid & 31) == 0) { ws[tid >> 5] = s; ws2[tid >> 5] = s2; }
    __syncthreads();
    if (tid < 32) {
        float a  = (tid < 8) ? ws[tid]  : 0.f;
        float a2 = (tid < 8) ? ws2[tid] : 0.f;
        #pragma unroll
        for (int o = 4; o > 0; o >>= 1) {
            a  += __shfl_xor_sync(0xffffffffu, a,  o);
            a2 += __shfl_xor_sync(0xffffffffu, a2, o);
        }
        if (tid == 0) { ws[0] = a; ws2[0] = a2; }
    }
    __syncthreads();
    float mean = ws[0] * (1.f / Dsz);
    float var  = ws2[0] * (1.f / Dsz) - mean * mean;
    float rstd = rsqrtf(var + 1e-5f);
    float4 gv = *(const float4*)(g  + tid * 4);
    float4 bv = *(const float4*)(be + tid * 4);
    float4 o;
    o.x = (v.x - mean) * rstd * gv.x + bv.x;
    o.y = (v.y - mean) * rstd * gv.y + bv.y;
    o.z = (v.z - mean) * rstd * gv.z + bv.z;
    o.w = (v.w - mean) * rstd * gv.w + bv.w;
    *(float4*)(out + (size_t)row * Dsz + tid * 4) = o;
}

// ---------------------------------------------------------------------------
// Launcher
// ---------------------------------------------------------------------------
extern "C" void kernel_launch(void* const* d_in, const int* in_sizes, int n_in,
                              void* d_out, int out_size)
{
    const int*   src  = (const int*)d_in[0];
    const int*   mask = (const int*)d_in[1];
    const float* tok  = (const float*)d_in[2];
    const float* pos  = (const float*)d_in[3];
    const float* Wq   = (const float*)d_in[4];
    const float* bq   = (const float*)d_in[5];
    const float* Wk   = (const float*)d_in[6];
    const float* bk   = (const float*)d_in[7];
    const float* Wv   = (const float*)d_in[8];
    const float* bv   = (const float*)d_in[9];
    const float* Wo   = (const float*)d_in[10];
    const float* bo   = (const float*)d_in[11];
    const float* g1   = (const float*)d_in[12];
    const float* be1  = (const float*)d_in[13];
    const float* g2   = (const float*)d_in[14];
    const float* be2  = (const float*)d_in[15];
    const float* W1   = (const float*)d_in[16];
    const float* bf1  = (const float*)d_in[17];
    const float* W2   = (const float*)d_in[18];
    const float* bf2  = (const float*)d_in[19];

    float* scratch = nullptr;
    cudaGetSymbolAddress((void**)&scratch, g_scratch);
    __nv_bfloat16 *AH, *AL, *BH, *BL;
    cudaGetSymbolAddress((void**)&AH, g_AH);
    cudaGetSymbolAddress((void**)&AL, g_AL);
    cudaGetSymbolAddress((void**)&BH, g_BH);
    cudaGetSymbolAddress((void**)&BL, g_BL);

    const size_t MD = (size_t)Msz * Dsz;
    float* x   = scratch;
    float* tmp = scratch + MD;
    float* q   = scratch + 2 * MD;
    float* k   = scratch + 3 * MD;
    float* v   = scratch + 4 * MD;
    float* ctx = scratch + 5 * MD;
    float* ff  = scratch + 6 * MD;

    const int FLASH_SMEM = 4 * FTILE * 4 + 64 * 4;
    cudaFuncSetAttribute(flash_kernel,
                         cudaFuncAttributeMaxDynamicSharedMemorySize, FLASH_SMEM);
    cudaFuncSetAttribute(gemm_tc,
                         cudaFuncAttributeMaxDynamicSharedMemorySize, GEMM_SMEM);

    embed_kernel<<<(Msz * Dsz) / 256, 256>>>(src, tok, pos, x);

    dim3 g_dd(Dsz / 128, Msz / 128);   // 8 x 32
    dim3 g_df(Fsz / 128, Msz / 128);   // 32 x 32
    dim3 g_fl(Ssz / 64, Hn, Bsz);

    const int n4_MD = Msz * Dsz / 4;   // 1,048,576
    const int n4_DD = Dsz * Dsz / 4;   // 262,144
    const int n4_DF = Dsz * Fsz / 4;   // 1,048,576
    const int n4_MF = Msz * Fsz / 4;   // 4,194,304

    for (int i = 0; i < Lnum; i++) {
        const float* Wqi = Wq + (size_t)i * Dsz * Dsz;
        const float* Wki = Wk + (size_t)i * Dsz * Dsz;
        const float* Wvi = Wv + (size_t)i * Dsz * Dsz;
        const float* Woi = Wo + (size_t)i * Dsz * Dsz;
        const float* W1i = W1 + (size_t)i * Dsz * Fsz;
        const float* W2i = W2 + (size_t)i * Fsz * Dsz;
        const float* bqi = bq + (size_t)i * Dsz;
        const float* bki = bk + (size_t)i * Dsz;
        const float* bvi = bv + (size_t)i * Dsz;
        const float* boi = bo + (size_t)i * Dsz;
        const float* b1i = bf1 + (size_t)i * Fsz;
        const float* b2i = bf2 + (size_t)i * Dsz;

        split_kernel<<<(n4_MD + 255) / 256, 256>>>(x, AH, AL, n4_MD);
        split_kernel<<<(n4_DD + 255) / 256, 256>>>(Wqi, BH, BL, n4_DD);
        gemm_tc<<<g_dd, 256, GEMM_SMEM>>>(AH, AL, BH, BL, bqi, nullptr, q, Dsz, Dsz, 0);
        split_kernel<<<(n4_DD + 255) / 256, 256>>>(Wki, BH, BL, n4_DD);
        gemm_tc<<<g_dd, 256, GEMM_SMEM>>>(AH, AL, BH, BL, bki, nullptr, k, Dsz, Dsz, 0);
        split_kernel<<<(n4_DD + 255) / 256, 256>>>(Wvi, BH, BL, n4_DD);
        gemm_tc<<<g_dd, 256, GEMM_SMEM>>>(AH, AL, BH, BL, bvi, nullptr, v, Dsz, Dsz, 0);

        flash_kernel<<<g_fl, 256, FLASH_SMEM>>>(q, k, v, mask, ctx);

        split_kernel<<<(n4_MD + 255) / 256, 256>>>(ctx, AH, AL, n4_MD);
        split_kernel<<<(n4_DD + 255) / 256, 256>>>(Woi, BH, BL, n4_DD);
        gemm_tc<<<g_dd, 256, GEMM_SMEM>>>(AH, AL, BH, BL, boi, x, tmp, Dsz, Dsz, 2);
        ln_kernel<<<Msz, 256>>>(tmp, g1 + (size_t)i * Dsz, be1 + (size_t)i * Dsz, x);

        split_kernel<<<(n4_MD + 255) / 256, 256>>>(x, AH, AL, n4_MD);
        split_kernel<<<(n4_DF + 255) / 256, 256>>>(W1i, BH, BL, n4_DF);
        gemm_tc<<<g_df, 256, GEMM_SMEM>>>(AH, AL, BH, BL, b1i, nullptr, ff, Fsz, Dsz, 1);

        split_kernel<<<(n4_MF + 255) / 256, 256>>>(ff, AH, AL, n4_MF);
        split_kernel<<<(n4_DF + 255) / 256, 256>>>(W2i, BH, BL, n4_DF);
        gemm_tc<<<g_dd, 256, GEMM_SMEM>>>(AH, AL, BH, BL, b2i, x, tmp, Dsz, Fsz, 2);

        float* lnout = (i == Lnum - 1) ? (float*)d_out : x;
        ln_kernel<<<Msz, 256>>>(tmp, g2 + (size_t)i * Dsz, be2 + (size_t)i * Dsz, lnout);
    }
}